// round 3
// baseline (speedup 1.0000x reference)
#include <cuda_runtime.h>
#include <cstdint>
#include <math.h>

#define Bb 128
#define Tt 25
#define Ee 512
#define Hh 1024
#define Vv 10000
#define Ff 2048

// ---------------- device scratch (no allocations allowed) ----------------
__device__ float g_wbuf[31211520];     // tf32-rounded weights
__device__ float g_featin[Bb*Ff];      // rounded features
__device__ float g_feat[Bb*Hh];        // leaky_relu(features@Wp+bp), rounded
__device__ float g_A0[Tt*Bb*1536];     // [emb_t | feat] for all t, rounded
__device__ float g_pre0[Tt*Bb*4096];   // precomputed input-part of layer0 gates (+bias)
__device__ float g_h0[Bb*Hh];
__device__ float g_c0[Bb*Hh];
__device__ float g_c1[Bb*Hh];
__device__ float g_comb1[Bb*2048];     // [h0new | h1]
__device__ float g_gates1[Bb*4096];
__device__ float g_hs[Tt*Bb*Hh];       // h1 outputs (rounded), t-major

// weight buffer offsets (floats)
#define OF_WP   0
#define OF_WF0  2097152
#define OF_WI0  4718592
#define OF_WO0  7340032
#define OF_WG0  9961472
#define OF_WF1  12582912
#define OF_WI1  14680064
#define OF_WO1  16777216
#define OF_WG1  18874368
#define OF_WOUT 20971520
#define REC_OFF 1572864   /* 1536*1024: recurrent rows of layer-0 weights */

__device__ __forceinline__ uint32_t f2tf(float x){
    uint32_t u; asm("cvt.rna.tf32.f32 %0, %1;" : "=r"(u) : "f"(x)); return u;
}
__device__ __forceinline__ float roundtf(float x){ return __uint_as_float(f2tf(x)); }
__device__ __forceinline__ float sigf(float x){ return 1.0f/(1.0f + expf(-x)); }

__device__ __forceinline__ void cp16(float* sdst, const float* gsrc, bool pred){
    uint32_t s = (uint32_t)__cvta_generic_to_shared(sdst);
    int sz = pred ? 16 : 0;
    asm volatile("cp.async.cg.shared.global [%0], [%1], 16, %2;\n" :: "r"(s), "l"(gsrc), "r"(sz));
}
__device__ __forceinline__ void cp_commit(){ asm volatile("cp.async.commit_group;\n"); }
__device__ __forceinline__ void cp_wait2(){ asm volatile("cp.async.wait_group 2;\n"); }

// ---------------- helper kernels ----------------
__global__ void cvt4_to_wbuf(const float* __restrict__ src, int off, int n4){
    int i = blockIdx.x*blockDim.x + threadIdx.x;
    if (i >= n4) return;
    float4 v = reinterpret_cast<const float4*>(src)[i];
    v.x = roundtf(v.x); v.y = roundtf(v.y); v.z = roundtf(v.z); v.w = roundtf(v.w);
    reinterpret_cast<float4*>(g_wbuf + off)[i] = v;
}

__global__ void cvt4_featin(const float* __restrict__ src, int n4){
    int i = blockIdx.x*blockDim.x + threadIdx.x;
    if (i >= n4) return;
    float4 v = reinterpret_cast<const float4*>(src)[i];
    v.x = roundtf(v.x); v.y = roundtf(v.y); v.z = roundtf(v.z); v.w = roundtf(v.w);
    reinterpret_cast<float4*>(g_featin)[i] = v;
}

__global__ void zero_state(){
    int i = blockIdx.x*blockDim.x + threadIdx.x;
    if (i < Bb*Hh){ g_h0[i]=0.f; g_c0[i]=0.f; g_c1[i]=0.f; }
    if (i < Bb*2048) g_comb1[i]=0.f;
}

__global__ void build_a0(const int* __restrict__ tokens, const float* __restrict__ emb){
    int idx = blockIdx.x*blockDim.x + threadIdx.x;
    if (idx >= Tt*Bb*1536) return;
    int row = idx / 1536;
    int col = idx - row*1536;
    int t = row >> 7;
    int b = row & 127;
    float v;
    if (col < Ee)
        v = roundtf(emb[(size_t)tokens[b*Tt + t]*Ee + col]);
    else
        v = g_feat[b*Hh + (col - Ee)];
    g_A0[idx] = v;
}

__global__ void pw_layer0(int t){
    int i = blockIdx.x*blockDim.x + threadIdx.x;   // 0..131071
    int b = i >> 10, h = i & 1023;
    const float* gb = g_pre0 + (size_t)t*(Bb*4096) + b*4096;
    float f  = sigf(gb[h]);
    float ii = sigf(gb[1024+h]);
    float o  = sigf(gb[2048+h]);
    float gg = tanhf(gb[3072+h]);
    float c = f*g_c0[i] + ii*gg;
    g_c0[i] = c;
    float hr = roundtf(o * tanhf(c));
    g_h0[i] = hr;
    g_comb1[b*2048 + h] = hr;
}

__global__ void pw_layer1(int t){
    int i = blockIdx.x*blockDim.x + threadIdx.x;
    int b = i >> 10, h = i & 1023;
    const float* gb = g_gates1 + b*4096;
    float f  = sigf(gb[h]);
    float ii = sigf(gb[1024+h]);
    float o  = sigf(gb[2048+h]);
    float gg = tanhf(gb[3072+h]);
    float c = f*g_c1[i] + ii*gg;
    g_c1[i] = c;
    float hr = roundtf(o * tanhf(c));
    g_comb1[b*2048 + 1024 + h] = hr;
    g_hs[(size_t)t*(Bb*Hh) + i] = hr;
}

// ---------------- TF32 GEMM ----------------
// C[M,N] = A[M,K] @ W[K,*] (+bias) (+C_old) ; N segmented into gates of width
// gateN, each gate a separate [K, gateN] row-major matrix with row stride ldw.
// mode bit0: leaky_relu + tf32 round. bit1: accumulate onto existing C.
// bit2: remap rows (t*128+b) -> (b*25+t) on store.
#define MODE_LEAKY 1
#define MODE_ACC   2
#define MODE_REMAP 4

__global__ __launch_bounds__(256) void gemm_tf32(
    const float* __restrict__ A, int lda, int K,
    const float* __restrict__ W0, const float* __restrict__ W1,
    const float* __restrict__ W2, const float* __restrict__ W3,
    const float* __restrict__ bp0, const float* __restrict__ bp1,
    const float* __restrict__ bp2, const float* __restrict__ bp3,
    float* __restrict__ C, int ldc, int N, int gateN, int ldw, int mode)
{
    __shared__ __align__(16) float As[4][64][20];
    __shared__ __align__(16) float Ws[4][16][72];

    const int n0 = blockIdx.x * 64;
    const int m0 = blockIdx.y * 64;
    const int gate = n0 / gateN;
    const float* __restrict__ W    = gate==0?W0 : gate==1?W1 : gate==2?W2 : W3;
    const float* __restrict__ bias = gate==0?bp0: gate==1?bp1: gate==2?bp2: bp3;
    const int nloc0 = n0 - gate*gateN;

    const int tid  = threadIdx.x;
    const int lane = tid & 31, warp = tid >> 5;
    const int wm = warp & 3, wn = warp >> 2;        // 4x2 warps, tile 16x32
    const int g  = lane >> 2, tg = lane & 3;

    const int ar = tid >> 2,  ac = (tid & 3)  * 4;  // A tile 64x16
    const int wr = tid >> 4,  wc = (tid & 15) * 4;  // W tile 16x64
    const bool wpred = (n0 + wc) < N;
    const float* wsrc0 = W + (size_t)wr*ldw + nloc0 + wc;

    float acc[4][4];
    #pragma unroll
    for (int i=0;i<4;i++){
        #pragma unroll
        for (int j=0;j<4;j++) acc[i][j]=0.f;
    }

    const int nk = K >> 4;

    #pragma unroll
    for (int s=0; s<3; ++s){
        cp16(&As[s][ar][ac], A + (size_t)(m0+ar)*lda + s*16 + ac, true);
        cp16(&Ws[s][wr][wc], wpred ? (wsrc0 + (size_t)(s*16)*ldw) : W, wpred);
        cp_commit();
    }

    for (int kt=0; kt<nk; ++kt){
        cp_wait2();
        __syncthreads();
        int kn = kt + 3;
        if (kn < nk){
            int sn = kn & 3;
            cp16(&As[sn][ar][ac], A + (size_t)(m0+ar)*lda + kn*16 + ac, true);
            cp16(&Ws[sn][wr][wc], wpred ? (wsrc0 + (size_t)(kn*16)*ldw) : W, wpred);
        }
        cp_commit();
        const int st = kt & 3;
        const int rr = wm*16 + g;
        #pragma unroll
        for (int kk=0; kk<2; ++kk){
            const int kc = kk*8 + tg;
            uint32_t a0 = __float_as_uint(As[st][rr  ][kc  ]);
            uint32_t a1 = __float_as_uint(As[st][rr+8][kc  ]);
            uint32_t a2 = __float_as_uint(As[st][rr  ][kc+4]);
            uint32_t a3 = __float_as_uint(As[st][rr+8][kc+4]);
            #pragma unroll
            for (int ni=0; ni<4; ++ni){
                const int nc = wn*32 + ni*8 + g;
                uint32_t b0 = __float_as_uint(Ws[st][kc  ][nc]);
                uint32_t b1 = __float_as_uint(Ws[st][kc+4][nc]);
                asm volatile(
                    "mma.sync.aligned.m16n8k8.row.col.f32.tf32.tf32.f32 "
                    "{%0,%1,%2,%3}, {%4,%5,%6,%7}, {%8,%9}, {%0,%1,%2,%3};\n"
                    : "+f"(acc[ni][0]), "+f"(acc[ni][1]),
                      "+f"(acc[ni][2]), "+f"(acc[ni][3])
                    : "r"(a0), "r"(a1), "r"(a2), "r"(a3), "r"(b0), "r"(b1));
            }
        }
    }

    // epilogue
    const int grow0 = m0 + wm*16 + g;
    const int grow1 = grow0 + 8;
    size_t drow0, drow1;
    if (mode & MODE_REMAP){
        drow0 = (size_t)((grow0 & 127)*Tt + (grow0 >> 7));
        drow1 = (size_t)((grow1 & 127)*Tt + (grow1 >> 7));
    } else { drow0 = (size_t)grow0; drow1 = (size_t)grow1; }
    float* C0 = C + drow0*ldc;
    float* C1 = C + drow1*ldc;

    #pragma unroll
    for (int ni=0; ni<4; ++ni){
        const int lcol = wn*32 + ni*8 + 2*tg;
        const int gcol = n0 + lcol;
        if (gcol >= N) continue;           // cols come in aligned even pairs, N even
        float v00=acc[ni][0], v01=acc[ni][1], v10=acc[ni][2], v11=acc[ni][3];
        if (bias){
            const int bi = nloc0 + lcol;
            float b0v = bias[bi], b1v = bias[bi+1];
            v00+=b0v; v01+=b1v; v10+=b0v; v11+=b1v;
        }
        if (mode & MODE_ACC){
            v00 += C0[gcol]; v01 += C0[gcol+1];
            v10 += C1[gcol]; v11 += C1[gcol+1];
        }
        if (mode & MODE_LEAKY){
            v00 = roundtf(v00 > 0.f ? v00 : 0.01f*v00);
            v01 = roundtf(v01 > 0.f ? v01 : 0.01f*v01);
            v10 = roundtf(v10 > 0.f ? v10 : 0.01f*v10);
            v11 = roundtf(v11 > 0.f ? v11 : 0.01f*v11);
        }
        C0[gcol] = v00; C0[gcol+1] = v01;
        C1[gcol] = v10; C1[gcol+1] = v11;
    }
}

// ---------------- host orchestration ----------------
extern "C" void kernel_launch(void* const* d_in, const int* in_sizes, int n_in,
                              void* d_out, int out_size)
{
    const int*   tokens    = (const int*)  d_in[0];
    const float* features  = (const float*)d_in[1];
    const float* embedding = (const float*)d_in[2];
    const float* Wp  = (const float*)d_in[3];
    const float* bp  = (const float*)d_in[4];
    const float* Wf0 = (const float*)d_in[5];  const float* bf0 = (const float*)d_in[6];
    const float* Wi0 = (const float*)d_in[7];  const float* bi0 = (const float*)d_in[8];
    const float* Wo0 = (const float*)d_in[9];  const float* bo0 = (const float*)d_in[10];
    const float* Wg0 = (const float*)d_in[11]; const float* bg0 = (const float*)d_in[12];
    const float* Wf1 = (const float*)d_in[13]; const float* bf1 = (const float*)d_in[14];
    const float* Wi1 = (const float*)d_in[15]; const float* bi1 = (const float*)d_in[16];
    const float* Wo1 = (const float*)d_in[17]; const float* bo1 = (const float*)d_in[18];
    const float* Wg1 = (const float*)d_in[19]; const float* bg1 = (const float*)d_in[20];
    const float* Wout = (const float*)d_in[21];
    const float* bout = (const float*)d_in[22];
    float* out = (float*)d_out;

    float *wb, *featin, *feat, *a0, *pre0, *h0, *comb1, *gates1, *hs;
    cudaGetSymbolAddress((void**)&wb,     g_wbuf);
    cudaGetSymbolAddress((void**)&featin, g_featin);
    cudaGetSymbolAddress((void**)&feat,   g_feat);
    cudaGetSymbolAddress((void**)&a0,     g_A0);
    cudaGetSymbolAddress((void**)&pre0,   g_pre0);
    cudaGetSymbolAddress((void**)&h0,     g_h0);
    cudaGetSymbolAddress((void**)&comb1,  g_comb1);
    cudaGetSymbolAddress((void**)&gates1, g_gates1);
    cudaGetSymbolAddress((void**)&hs,     g_hs);

    // 1) round all GEMM operands to tf32
    cvt4_featin<<<(Bb*Ff/4 + 255)/256, 256>>>(features, Bb*Ff/4);
    cvt4_to_wbuf<<<(Ff*Hh/4 + 255)/256, 256>>>(Wp,  OF_WP,  Ff*Hh/4);
    cvt4_to_wbuf<<<(2560*1024/4 + 255)/256, 256>>>(Wf0, OF_WF0, 2560*1024/4);
    cvt4_to_wbuf<<<(2560*1024/4 + 255)/256, 256>>>(Wi0, OF_WI0, 2560*1024/4);
    cvt4_to_wbuf<<<(2560*1024/4 + 255)/256, 256>>>(Wo0, OF_WO0, 2560*1024/4);
    cvt4_to_wbuf<<<(2560*1024/4 + 255)/256, 256>>>(Wg0, OF_WG0, 2560*1024/4);
    cvt4_to_wbuf<<<(2048*1024/4 + 255)/256, 256>>>(Wf1, OF_WF1, 2048*1024/4);
    cvt4_to_wbuf<<<(2048*1024/4 + 255)/256, 256>>>(Wi1, OF_WI1, 2048*1024/4);
    cvt4_to_wbuf<<<(2048*1024/4 + 255)/256, 256>>>(Wo1, OF_WO1, 2048*1024/4);
    cvt4_to_wbuf<<<(2048*1024/4 + 255)/256, 256>>>(Wg1, OF_WG1, 2048*1024/4);
    cvt4_to_wbuf<<<(1024*10000/4 + 255)/256, 256>>>(Wout, OF_WOUT, 1024*10000/4);

    zero_state<<<(Bb*2048 + 255)/256, 256>>>();

    // 2) feature projection: [128,1024] = leaky(featin @ Wp + bp), rounded
    gemm_tf32<<<dim3(16,2), 256>>>(featin, Ff, Ff,
        wb+OF_WP, wb+OF_WP, wb+OF_WP, wb+OF_WP,
        bp, nullptr, nullptr, nullptr,
        feat, Hh, Hh, Hh, Hh, MODE_LEAKY);

    // 3) build A0 = [emb_t | feat] for all t  -> [3200,1536]
    build_a0<<<(Tt*Bb*1536 + 255)/256, 256>>>(tokens, embedding);

    // 4) pre0 = A0 @ W*0[0:1536,:] + b*0   -> [3200,4096]
    gemm_tf32<<<dim3(64,50), 256>>>(a0, 1536, 1536,
        wb+OF_WF0, wb+OF_WI0, wb+OF_WO0, wb+OF_WG0,
        bf0, bi0, bo0, bg0,
        pre0, 4096, 4096, 1024, 1024, 0);

    // 5) sequential recurrence
    for (int t = 0; t < Tt; ++t){
        // gates0 = pre0[t] + h0 @ W*0[1536:,:]   (in place)
        gemm_tf32<<<dim3(64,2), 256>>>(h0, Hh, Hh,
            wb+OF_WF0+REC_OFF, wb+OF_WI0+REC_OFF, wb+OF_WO0+REC_OFF, wb+OF_WG0+REC_OFF,
            nullptr, nullptr, nullptr, nullptr,
            pre0 + (size_t)t*(Bb*4096), 4096, 4096, 1024, 1024, MODE_ACC);
        pw_layer0<<<512, 256>>>(t);
        // gates1 = [h0new | h1] @ W*1 + b*1
        gemm_tf32<<<dim3(64,2), 256>>>(comb1, 2048, 2048,
            wb+OF_WF1, wb+OF_WI1, wb+OF_WO1, wb+OF_WG1,
            bf1, bi1, bo1, bg1,
            gates1, 4096, 4096, 1024, 1024, 0);
        pw_layer1<<<512, 256>>>(t);
    }

    // 6) logits = hs @ Wout + bout, remapped to [B,T,V]
    //    ldw = 10000 (true Wout row stride), gateN huge -> single gate
    gemm_tf32<<<dim3(157,50), 256>>>(hs, Hh, Hh,
        wb+OF_WOUT, wb+OF_WOUT, wb+OF_WOUT, wb+OF_WOUT,
        bout, nullptr, nullptr, nullptr,
        out, Vv, Vv, 1<<30, Vv, MODE_REMAP);
}

// round 4
// speedup vs baseline: 1.0004x; 1.0004x over previous
#include <cuda_runtime.h>
#include <cstdint>
#include <math.h>

#define Bb 128
#define Tt 25
#define Ee 512
#define Hh 1024
#define Vv 10000
#define Ff 2048

// ---------------- device scratch ----------------
__device__ float g_wbuf[31211520];     // tf32-rounded weights
__device__ float g_featin[Bb*Ff];
__device__ float g_feat[Bb*Hh];
__device__ float g_A0[Tt*Bb*1536];
__device__ float g_pre0[Tt*Bb*4096];   // interleaved gate cols, +bias
__device__ float g_c0[Bb*Hh];
__device__ float g_c1[Bb*Hh];
__device__ float g_comb1[Bb*2048];     // [h0 | h1]
__device__ float g_hs[Tt*Bb*Hh];
__device__ float g_part[128*4096];     // k-split partial tiles
__device__ float g_bias0i[4096];
__device__ float g_bias1i[4096];
__device__ unsigned g_barc;

// wbuf offsets (floats)
#define OF_WP   0
#define OF_W0I  2097152      /* 2560x4096 interleaved */
#define OF_W1I  12582912     /* 2048x4096 interleaved */
#define OF_WOUT 20971520     /* 1024x10000 */

__device__ __forceinline__ uint32_t f2tf(float x){
    uint32_t u; asm("cvt.rna.tf32.f32 %0, %1;" : "=r"(u) : "f"(x)); return u;
}
__device__ __forceinline__ float roundtf(float x){ return __uint_as_float(f2tf(x)); }
__device__ __forceinline__ float sigf(float x){ return 1.0f/(1.0f + expf(-x)); }

__device__ __forceinline__ void cp16(float* sdst, const float* gsrc){
    uint32_t s = (uint32_t)__cvta_generic_to_shared(sdst);
    asm volatile("cp.async.cg.shared.global [%0], [%1], 16;\n" :: "r"(s), "l"(gsrc));
}
__device__ __forceinline__ void cp16p(float* sdst, const float* gsrc, bool pred){
    uint32_t s = (uint32_t)__cvta_generic_to_shared(sdst);
    int sz = pred ? 16 : 0;
    asm volatile("cp.async.cg.shared.global [%0], [%1], 16, %2;\n" :: "r"(s), "l"(gsrc), "r"(sz));
}
__device__ __forceinline__ void cp_commit(){ asm volatile("cp.async.commit_group;\n"); }
__device__ __forceinline__ void cp_wait2(){ asm volatile("cp.async.wait_group 2;\n"); }
__device__ __forceinline__ void cp_wait0(){ asm volatile("cp.async.wait_group 0;\n"); }

// ---------------- one-shot convert / pack kernel ----------------
#define S_FEAT 65536
#define S_WP   524288
#define S_WOUT 2560000
#define S_W0I  2621440
#define S_W1I  2097152
#define CVT_TOTAL (S_FEAT+S_WP+S_WOUT+S_W0I+S_W1I+1024+1024)

__global__ void cvt_all(
    const float* __restrict__ features, const float* __restrict__ Wp,
    const float* __restrict__ Wout,
    const float* __restrict__ Wf0, const float* __restrict__ Wi0,
    const float* __restrict__ Wo0, const float* __restrict__ Wg0,
    const float* __restrict__ Wf1, const float* __restrict__ Wi1,
    const float* __restrict__ Wo1, const float* __restrict__ Wg1,
    const float* __restrict__ bf0, const float* __restrict__ bi0,
    const float* __restrict__ bo0, const float* __restrict__ bg0,
    const float* __restrict__ bf1, const float* __restrict__ bi1,
    const float* __restrict__ bo1, const float* __restrict__ bg1)
{
    int i = blockIdx.x*blockDim.x + threadIdx.x;
    if (i >= CVT_TOTAL) return;
    if (i < S_FEAT){
        float4 v = reinterpret_cast<const float4*>(features)[i];
        v.x=roundtf(v.x); v.y=roundtf(v.y); v.z=roundtf(v.z); v.w=roundtf(v.w);
        reinterpret_cast<float4*>(g_featin)[i] = v; return;
    }
    i -= S_FEAT;
    if (i < S_WP){
        float4 v = reinterpret_cast<const float4*>(Wp)[i];
        v.x=roundtf(v.x); v.y=roundtf(v.y); v.z=roundtf(v.z); v.w=roundtf(v.w);
        reinterpret_cast<float4*>(g_wbuf + OF_WP)[i] = v; return;
    }
    i -= S_WP;
    if (i < S_WOUT){
        float4 v = reinterpret_cast<const float4*>(Wout)[i];
        v.x=roundtf(v.x); v.y=roundtf(v.y); v.z=roundtf(v.z); v.w=roundtf(v.w);
        reinterpret_cast<float4*>(g_wbuf + OF_WOUT)[i] = v; return;
    }
    i -= S_WOUT;
    if (i < S_W0I){
        int k = i >> 10, h = i & 1023;
        int s = k*1024 + h;
        float4 v;
        v.x = roundtf(Wf0[s]); v.y = roundtf(Wi0[s]);
        v.z = roundtf(Wo0[s]); v.w = roundtf(Wg0[s]);
        reinterpret_cast<float4*>(g_wbuf + OF_W0I)[(size_t)k*1024 + h] = v; return;
    }
    i -= S_W0I;
    if (i < S_W1I){
        int k = i >> 10, h = i & 1023;
        int s = k*1024 + h;
        float4 v;
        v.x = roundtf(Wf1[s]); v.y = roundtf(Wi1[s]);
        v.z = roundtf(Wo1[s]); v.w = roundtf(Wg1[s]);
        reinterpret_cast<float4*>(g_wbuf + OF_W1I)[(size_t)k*1024 + h] = v; return;
    }
    i -= S_W1I;
    if (i < 1024){
        float4 v; v.x=bf0[i]; v.y=bi0[i]; v.z=bo0[i]; v.w=bg0[i];
        reinterpret_cast<float4*>(g_bias0i)[i] = v; return;
    }
    i -= 1024;
    {
        float4 v; v.x=bf1[i]; v.y=bi1[i]; v.z=bo1[i]; v.w=bg1[i];
        reinterpret_cast<float4*>(g_bias1i)[i] = v;
    }
}

__global__ void zero_state(){
    int i = blockIdx.x*blockDim.x + threadIdx.x;
    if (i == 0) g_barc = 0u;
    if (i < Bb*Hh){ g_c0[i]=0.f; g_c1[i]=0.f; }
    if (i < Bb*2048) g_comb1[i]=0.f;
}

__global__ void build_a0(const int* __restrict__ tokens, const float* __restrict__ emb){
    int idx = blockIdx.x*blockDim.x + threadIdx.x;
    if (idx >= Tt*Bb*1536) return;
    int row = idx / 1536;
    int col = idx - row*1536;
    int t = row >> 7;
    int b = row & 127;
    float v;
    if (col < Ee) v = roundtf(emb[(size_t)tokens[b*Tt + t]*Ee + col]);
    else          v = g_feat[b*Hh + (col - Ee)];
    g_A0[idx] = v;
}

// ---------------- standalone TF32 GEMM (feat / pre0 / out) ----------------
#define MODE_LEAKY 1
#define MODE_REMAP 4

__global__ __launch_bounds__(256) void gemm_tf32(
    const float* __restrict__ A, int lda, int K,
    const float* __restrict__ W, int ldw,
    const float* __restrict__ bias,
    float* __restrict__ C, int ldc, int N, int mode)
{
    __shared__ __align__(16) float As[4][64][20];
    __shared__ __align__(16) float Ws[4][16][72];

    const int n0 = blockIdx.x * 64;
    const int m0 = blockIdx.y * 64;
    const int tid  = threadIdx.x;
    const int lane = tid & 31, warp = tid >> 5;
    const int wm = warp & 3, wn = warp >> 2;
    const int g  = lane >> 2, tg = lane & 3;
    const int ar = tid >> 2,  ac = (tid & 3)  * 4;
    const int wr = tid >> 4,  wc = (tid & 15) * 4;
    const bool wpred = (n0 + wc) < N;
    const float* wsrc0 = W + (size_t)wr*ldw + n0 + wc;

    float acc[4][4];
    #pragma unroll
    for (int i=0;i<4;i++){
        #pragma unroll
        for (int j=0;j<4;j++) acc[i][j]=0.f;
    }

    const int nk = K >> 4;
    #pragma unroll
    for (int s=0; s<3; ++s){
        cp16(&As[s][ar][ac], A + (size_t)(m0+ar)*lda + s*16 + ac);
        cp16p(&Ws[s][wr][wc], wpred ? (wsrc0 + (size_t)(s*16)*ldw) : W, wpred);
        cp_commit();
    }
    for (int kt=0; kt<nk; ++kt){
        cp_wait2();
        __syncthreads();
        int kn = kt + 3;
        if (kn < nk){
            int sn = kn & 3;
            cp16(&As[sn][ar][ac], A + (size_t)(m0+ar)*lda + kn*16 + ac);
            cp16p(&Ws[sn][wr][wc], wpred ? (wsrc0 + (size_t)(kn*16)*ldw) : W, wpred);
        }
        cp_commit();
        const int st = kt & 3;
        const int rr = wm*16 + g;
        #pragma unroll
        for (int kk=0; kk<2; ++kk){
            const int kc = kk*8 + tg;
            uint32_t a0 = __float_as_uint(As[st][rr  ][kc  ]);
            uint32_t a1 = __float_as_uint(As[st][rr+8][kc  ]);
            uint32_t a2 = __float_as_uint(As[st][rr  ][kc+4]);
            uint32_t a3 = __float_as_uint(As[st][rr+8][kc+4]);
            #pragma unroll
            for (int ni=0; ni<4; ++ni){
                const int nc = wn*32 + ni*8 + g;
                uint32_t b0 = __float_as_uint(Ws[st][kc  ][nc]);
                uint32_t b1 = __float_as_uint(Ws[st][kc+4][nc]);
                asm volatile(
                    "mma.sync.aligned.m16n8k8.row.col.f32.tf32.tf32.f32 "
                    "{%0,%1,%2,%3}, {%4,%5,%6,%7}, {%8,%9}, {%0,%1,%2,%3};\n"
                    : "+f"(acc[ni][0]), "+f"(acc[ni][1]),
                      "+f"(acc[ni][2]), "+f"(acc[ni][3])
                    : "r"(a0), "r"(a1), "r"(a2), "r"(a3), "r"(b0), "r"(b1));
            }
        }
    }

    const int grow0 = m0 + wm*16 + g;
    const int grow1 = grow0 + 8;
    size_t drow0, drow1;
    if (mode & MODE_REMAP){
        drow0 = (size_t)((grow0 & 127)*Tt + (grow0 >> 7));
        drow1 = (size_t)((grow1 & 127)*Tt + (grow1 >> 7));
    } else { drow0 = (size_t)grow0; drow1 = (size_t)grow1; }
    float* C0 = C + drow0*ldc;
    float* C1 = C + drow1*ldc;

    #pragma unroll
    for (int ni=0; ni<4; ++ni){
        const int lcol = wn*32 + ni*8 + 2*tg;
        const int gcol = n0 + lcol;
        if (gcol >= N) continue;
        float v00=acc[ni][0], v01=acc[ni][1], v10=acc[ni][2], v11=acc[ni][3];
        float b0v = bias[gcol], b1v = bias[gcol+1];
        v00+=b0v; v01+=b1v; v10+=b0v; v11+=b1v;
        if (mode & MODE_LEAKY){
            v00 = roundtf(v00 > 0.f ? v00 : 0.01f*v00);
            v01 = roundtf(v01 > 0.f ? v01 : 0.01f*v01);
            v10 = roundtf(v10 > 0.f ? v10 : 0.01f*v10);
            v11 = roundtf(v11 > 0.f ? v11 : 0.01f*v11);
        }
        C0[gcol] = v00; C0[gcol+1] = v01;
        C1[gcol] = v10; C1[gcol+1] = v11;
    }
}

// ---------------- persistent recurrence ----------------
#define NCTA 256u

__device__ __forceinline__ void gridbar(unsigned &ep){
    __syncthreads();
    ep += 1;
    if (threadIdx.x == 0){
        __threadfence();
        atomicAdd(&g_barc, 1u);
        unsigned tgt = ep * NCTA;
        unsigned v;
        do {
            asm volatile("ld.acquire.gpu.u32 %0, [%1];" : "=r"(v) : "l"(&g_barc) : "memory");
        } while (v < tgt);
    }
    __syncthreads();
}

__device__ __forceinline__ void gemm_tile_dev(
    const float* __restrict__ A, int lda,
    const float* __restrict__ W, int ldw,
    int m0, int n0, int kbase, int nk,
    float (&As)[4][64][20], float (&Ws)[4][16][72],
    float acc[4][4])
{
    const int tid  = threadIdx.x;
    const int lane = tid & 31, warp = tid >> 5;
    const int wm = warp & 3, wn = warp >> 2;
    const int g  = lane >> 2, tg = lane & 3;
    const int ar = tid >> 2,  ac = (tid & 3)  * 4;
    const int wr = tid >> 4,  wc = (tid & 15) * 4;
    const float* asrc = A + (size_t)(m0+ar)*lda + kbase + ac;
    const float* wsrc = W + (size_t)(kbase+wr)*ldw + n0 + wc;

    #pragma unroll
    for (int i=0;i<4;i++){
        #pragma unroll
        for (int j=0;j<4;j++) acc[i][j]=0.f;
    }

    #pragma unroll
    for (int s=0; s<3; ++s){
        cp16(&As[s][ar][ac], asrc + s*16);
        cp16(&Ws[s][wr][wc], wsrc + (size_t)(s*16)*ldw);
        cp_commit();
    }
    for (int kt=0; kt<nk; ++kt){
        cp_wait2();
        __syncthreads();
        int kn = kt + 3;
        if (kn < nk){
            int sn = kn & 3;
            cp16(&As[sn][ar][ac], asrc + kn*16);
            cp16(&Ws[sn][wr][wc], wsrc + (size_t)(kn*16)*ldw);
        }
        cp_commit();
        const int st = kt & 3;
        const int rr = wm*16 + g;
        #pragma unroll
        for (int kk=0; kk<2; ++kk){
            const int kc = kk*8 + tg;
            uint32_t a0 = __float_as_uint(As[st][rr  ][kc  ]);
            uint32_t a1 = __float_as_uint(As[st][rr+8][kc  ]);
            uint32_t a2 = __float_as_uint(As[st][rr  ][kc+4]);
            uint32_t a3 = __float_as_uint(As[st][rr+8][kc+4]);
            #pragma unroll
            for (int ni=0; ni<4; ++ni){
                const int nc = wn*32 + ni*8 + g;
                uint32_t b0 = __float_as_uint(Ws[st][kc  ][nc]);
                uint32_t b1 = __float_as_uint(Ws[st][kc+4][nc]);
                asm volatile(
                    "mma.sync.aligned.m16n8k8.row.col.f32.tf32.tf32.f32 "
                    "{%0,%1,%2,%3}, {%4,%5,%6,%7}, {%8,%9}, {%0,%1,%2,%3};\n"
                    : "+f"(acc[ni][0]), "+f"(acc[ni][1]),
                      "+f"(acc[ni][2]), "+f"(acc[ni][3])
                    : "r"(a0), "r"(a1), "r"(a2), "r"(a3), "r"(b0), "r"(b1));
            }
        }
    }
    cp_wait0();
    __syncthreads();
}

__device__ __forceinline__ void store_partial(float acc[4][4], int tile,
                                              int wm, int wn, int g, int tg)
{
    float* gp = g_part + (size_t)tile*4096;
    const int lr0 = wm*16 + g, lr1 = lr0 + 8;
    #pragma unroll
    for (int ni=0; ni<4; ++ni){
        const int lc = wn*32 + ni*8 + 2*tg;
        gp[lr0*64 + lc]   = acc[ni][0];
        gp[lr0*64 + lc+1] = acc[ni][1];
        gp[lr1*64 + lc]   = acc[ni][2];
        gp[lr1*64 + lc+1] = acc[ni][3];
    }
}

// ks==0 combine + LSTM pointwise. rowext != 0: per-row extra (pre0 tile,
// stride 4096); else colext = per-col bias. hoff: comb1 col offset.
__device__ __forceinline__ void lstm_epi(float acc[4][4], int tile, int t,
    const float* rowext, const float* colext,
    float* cbuf, int hoff, bool write_hs,
    int m0, int n0, int nb, int wm, int wn, int g, int tg)
{
    const float* gp = g_part + (size_t)tile*4096;
    const int lr0 = wm*16 + g, lr1 = lr0 + 8;
    const int grow0 = m0 + lr0, grow1 = m0 + lr1;
    #pragma unroll
    for (int ni=0; ni<4; ++ni){
        const int lc = wn*32 + ni*8 + 2*tg;
        const int gcol = n0 + lc;
        float v00 = acc[ni][0] + gp[lr0*64 + lc];
        float v01 = acc[ni][1] + gp[lr0*64 + lc+1];
        float v10 = acc[ni][2] + gp[lr1*64 + lc];
        float v11 = acc[ni][3] + gp[lr1*64 + lc+1];
        if (rowext){
            v00 += rowext[(size_t)grow0*4096 + gcol];
            v01 += rowext[(size_t)grow0*4096 + gcol+1];
            v10 += rowext[(size_t)grow1*4096 + gcol];
            v11 += rowext[(size_t)grow1*4096 + gcol+1];
        } else {
            float b0 = colext[gcol], b1 = colext[gcol+1];
            v00+=b0; v01+=b1; v10+=b0; v11+=b1;
        }
        float p00 = __shfl_xor_sync(0xffffffffu, v00, 1);
        float p01 = __shfl_xor_sync(0xffffffffu, v01, 1);
        float p10 = __shfl_xor_sync(0xffffffffu, v10, 1);
        float p11 = __shfl_xor_sync(0xffffffffu, v11, 1);
        if ((tg & 1) == 0){
            const int h = nb*16 + wn*8 + ni*2 + (tg >> 1);
            // row 0
            {
                float f = sigf(v00), ii = sigf(v01);
                float o = sigf(p00), gg = tanhf(p01);
                float c = f*cbuf[grow0*1024 + h] + ii*gg;
                cbuf[grow0*1024 + h] = c;
                float hn = roundtf(o * tanhf(c));
                g_comb1[grow0*2048 + hoff + h] = hn;
                if (write_hs) g_hs[(size_t)t*(Bb*Hh) + grow0*1024 + h] = hn;
            }
            // row 1
            {
                float f = sigf(v10), ii = sigf(v11);
                float o = sigf(p10), gg = tanhf(p11);
                float c = f*cbuf[grow1*1024 + h] + ii*gg;
                cbuf[grow1*1024 + h] = c;
                float hn = roundtf(o * tanhf(c));
                g_comb1[grow1*2048 + hoff + h] = hn;
                if (write_hs) g_hs[(size_t)t*(Bb*Hh) + grow1*1024 + h] = hn;
            }
        }
    }
}

__global__ __launch_bounds__(256, 2) void lstm_persistent()
{
    __shared__ __align__(16) float As[4][64][20];
    __shared__ __align__(16) float Ws[4][16][72];

    const int cta  = blockIdx.x;
    const int ks   = cta & 1;
    const int tile = cta >> 1;            // 0..127
    const int mb   = tile & 1, nb = tile >> 1;
    const int m0   = mb*64,   n0 = nb*64;
    const int tid  = threadIdx.x;
    const int lane = tid & 31, warp = tid >> 5;
    const int wm = warp & 3, wn = warp >> 2;
    const int g  = lane >> 2, tg = lane & 3;

    const float* Wrec0 = g_wbuf + OF_W0I + (size_t)1536*4096;
    const float* W1    = g_wbuf + OF_W1I;

    unsigned ep = 0;
    float acc[4][4];

    for (int t = 0; t < Tt; ++t){
        // layer 0 recurrent: K=1024 over comb1[:,0:1024)
        gemm_tile_dev(g_comb1, 2048, Wrec0, 4096, m0, n0, ks*512, 32, As, Ws, acc);
        if (ks == 1) store_partial(acc, tile, wm, wn, g, tg);
        gridbar(ep);
        if (ks == 0)
            lstm_epi(acc, tile, t, g_pre0 + (size_t)t*(Bb*4096), nullptr,
                     g_c0, 0, false, m0, n0, nb, wm, wn, g, tg);
        gridbar(ep);
        // layer 1: K=2048 over comb1
        gemm_tile_dev(g_comb1, 2048, W1, 4096, m0, n0, ks*1024, 64, As, Ws, acc);
        if (ks == 1) store_partial(acc, tile, wm, wn, g, tg);
        gridbar(ep);
        if (ks == 0)
            lstm_epi(acc, tile, t, nullptr, g_bias1i,
                     g_c1, 1024, true, m0, n0, nb, wm, wn, g, tg);
        gridbar(ep);
    }
}

// ---------------- host orchestration ----------------
extern "C" void kernel_launch(void* const* d_in, const int* in_sizes, int n_in,
                              void* d_out, int out_size)
{
    const int*   tokens    = (const int*)  d_in[0];
    const float* features  = (const float*)d_in[1];
    const float* embedding = (const float*)d_in[2];
    const float* Wp  = (const float*)d_in[3];
    const float* bp  = (const float*)d_in[4];
    const float* Wf0 = (const float*)d_in[5];  const float* bf0 = (const float*)d_in[6];
    const float* Wi0 = (const float*)d_in[7];  const float* bi0 = (const float*)d_in[8];
    const float* Wo0 = (const float*)d_in[9];  const float* bo0 = (const float*)d_in[10];
    const float* Wg0 = (const float*)d_in[11]; const float* bg0 = (const float*)d_in[12];
    const float* Wf1 = (const float*)d_in[13]; const float* bf1 = (const float*)d_in[14];
    const float* Wi1 = (const float*)d_in[15]; const float* bi1 = (const float*)d_in[16];
    const float* Wo1 = (const float*)d_in[17]; const float* bo1 = (const float*)d_in[18];
    const float* Wg1 = (const float*)d_in[19]; const float* bg1 = (const float*)d_in[20];
    const float* Wout = (const float*)d_in[21];
    const float* bout = (const float*)d_in[22];
    float* out = (float*)d_out;

    float *wb, *featin, *feat, *a0, *pre0, *hs, *b0i;
    cudaGetSymbolAddress((void**)&wb,     g_wbuf);
    cudaGetSymbolAddress((void**)&featin, g_featin);
    cudaGetSymbolAddress((void**)&feat,   g_feat);
    cudaGetSymbolAddress((void**)&a0,     g_A0);
    cudaGetSymbolAddress((void**)&pre0,   g_pre0);
    cudaGetSymbolAddress((void**)&hs,     g_hs);
    cudaGetSymbolAddress((void**)&b0i,    g_bias0i);

    // 1) convert + pack everything (single launch)
    cvt_all<<<(CVT_TOTAL + 255)/256, 256>>>(features, Wp, Wout,
        Wf0, Wi0, Wo0, Wg0, Wf1, Wi1, Wo1, Wg1,
        bf0, bi0, bo0, bg0, bf1, bi1, bo1, bg1);

    // 2) zero state + barrier counter
    zero_state<<<(Bb*2048 + 255)/256, 256>>>();

    // 3) feature projection
    gemm_tf32<<<dim3(16,2), 256>>>(featin, Ff, Ff,
        wb + OF_WP, Hh, bp, feat, Hh, Hh, MODE_LEAKY);

    // 4) A0 = [emb_t | feat]
    build_a0<<<(Tt*Bb*1536 + 255)/256, 256>>>(tokens, embedding);

    // 5) pre0 = A0 @ W0i[0:1536,:] + bias0i  (interleaved gate cols)
    gemm_tf32<<<dim3(64,50), 256>>>(a0, 1536, 1536,
        wb + OF_W0I, 4096, b0i, pre0, 4096, 4096, 0);

    // 6) persistent 25-step recurrence (launch #6 -> profiled by ncu -s 5)
    lstm_persistent<<<NCTA, 256>>>();

    // 7) logits = hs @ Wout + bout, remap to [B,T,V]
    gemm_tf32<<<dim3(157,50), 256>>>(hs, Hh, Hh,
        wb + OF_WOUT, Vv, bout, out, Vv, Vv, MODE_REMAP);
}

// round 5
// speedup vs baseline: 1.0197x; 1.0192x over previous
#include <cuda_runtime.h>
#include <cstdint>
#include <math.h>

#define Bb 128
#define Tt 25
#define Ee 512
#define Hh 1024
#define Vv 10000
#define Ff 2048

// ---------------- device scratch ----------------
__device__ float g_wbuf[31211520];     // tf32-rounded weights
__device__ float g_featin[Bb*Ff];
__device__ float g_feat[Bb*Hh];
__device__ float g_A0[Tt*Bb*1536];
__device__ float g_pre0[Tt*Bb*4096];   // interleaved gate cols, +bias
__device__ float g_c0[Bb*Hh];
__device__ float g_c1[Bb*Hh];
__device__ float g_comb1[Bb*2048];     // [h0 | h1]
__device__ float g_hs[Tt*Bb*Hh];
__device__ float g_part[128*4096];     // k-split partial tiles
__device__ float g_bias0i[4096];
__device__ float g_bias1i[4096];
__device__ unsigned g_barc;

// wbuf offsets (floats)
#define OF_WP   0
#define OF_W0I  2097152      /* 2560x4096 interleaved */
#define OF_W1I  12582912     /* 2048x4096 interleaved */
#define OF_WOUT 20971520     /* 1024x10000 */

__device__ __forceinline__ uint32_t f2tf(float x){
    uint32_t u; asm("cvt.rna.tf32.f32 %0, %1;" : "=r"(u) : "f"(x)); return u;
}
__device__ __forceinline__ float roundtf(float x){ return __uint_as_float(f2tf(x)); }
__device__ __forceinline__ float sigf(float x){ return 1.0f/(1.0f + expf(-x)); }

__device__ __forceinline__ void cp16(float* sdst, const float* gsrc){
    uint32_t s = (uint32_t)__cvta_generic_to_shared(sdst);
    asm volatile("cp.async.cg.shared.global [%0], [%1], 16;\n" :: "r"(s), "l"(gsrc));
}
__device__ __forceinline__ void cp16p(float* sdst, const float* gsrc, bool pred){
    uint32_t s = (uint32_t)__cvta_generic_to_shared(sdst);
    int sz = pred ? 16 : 0;
    asm volatile("cp.async.cg.shared.global [%0], [%1], 16, %2;\n" :: "r"(s), "l"(gsrc), "r"(sz));
}
__device__ __forceinline__ void cp_commit(){ asm volatile("cp.async.commit_group;\n"); }
__device__ __forceinline__ void cp_wait2(){ asm volatile("cp.async.wait_group 2;\n"); }
__device__ __forceinline__ void cp_wait0(){ asm volatile("cp.async.wait_group 0;\n"); }

// ---------------- one-shot convert / pack / zero kernel ----------------
#define S_FEAT 65536
#define S_WP   524288
#define S_WOUT 2560000
#define S_W0I  2621440
#define S_W1I  2097152
#define S_B    1024
#define S_Z    131073   /* zero c0,c1,comb1 as float4 + barc */
#define CVT_TOTAL (S_FEAT+S_WP+S_WOUT+S_W0I+S_W1I+2*S_B+S_Z)

__global__ void cvt_all(
    const float* __restrict__ features, const float* __restrict__ Wp,
    const float* __restrict__ Wout,
    const float* __restrict__ Wf0, const float* __restrict__ Wi0,
    const float* __restrict__ Wo0, const float* __restrict__ Wg0,
    const float* __restrict__ Wf1, const float* __restrict__ Wi1,
    const float* __restrict__ Wo1, const float* __restrict__ Wg1,
    const float* __restrict__ bf0, const float* __restrict__ bi0,
    const float* __restrict__ bo0, const float* __restrict__ bg0,
    const float* __restrict__ bf1, const float* __restrict__ bi1,
    const float* __restrict__ bo1, const float* __restrict__ bg1)
{
    int i = blockIdx.x*blockDim.x + threadIdx.x;
    if (i >= CVT_TOTAL) return;
    if (i < S_FEAT){
        float4 v = reinterpret_cast<const float4*>(features)[i];
        v.x=roundtf(v.x); v.y=roundtf(v.y); v.z=roundtf(v.z); v.w=roundtf(v.w);
        reinterpret_cast<float4*>(g_featin)[i] = v; return;
    }
    i -= S_FEAT;
    if (i < S_WP){
        float4 v = reinterpret_cast<const float4*>(Wp)[i];
        v.x=roundtf(v.x); v.y=roundtf(v.y); v.z=roundtf(v.z); v.w=roundtf(v.w);
        reinterpret_cast<float4*>(g_wbuf + OF_WP)[i] = v; return;
    }
    i -= S_WP;
    if (i < S_WOUT){
        float4 v = reinterpret_cast<const float4*>(Wout)[i];
        v.x=roundtf(v.x); v.y=roundtf(v.y); v.z=roundtf(v.z); v.w=roundtf(v.w);
        reinterpret_cast<float4*>(g_wbuf + OF_WOUT)[i] = v; return;
    }
    i -= S_WOUT;
    if (i < S_W0I){
        int k = i >> 10, h = i & 1023;
        int s = k*1024 + h;
        float4 v;
        v.x = roundtf(Wf0[s]); v.y = roundtf(Wi0[s]);
        v.z = roundtf(Wo0[s]); v.w = roundtf(Wg0[s]);
        reinterpret_cast<float4*>(g_wbuf + OF_W0I)[(size_t)k*1024 + h] = v; return;
    }
    i -= S_W0I;
    if (i < S_W1I){
        int k = i >> 10, h = i & 1023;
        int s = k*1024 + h;
        float4 v;
        v.x = roundtf(Wf1[s]); v.y = roundtf(Wi1[s]);
        v.z = roundtf(Wo1[s]); v.w = roundtf(Wg1[s]);
        reinterpret_cast<float4*>(g_wbuf + OF_W1I)[(size_t)k*1024 + h] = v; return;
    }
    i -= S_W1I;
    if (i < S_B){
        float4 v; v.x=bf0[i]; v.y=bi0[i]; v.z=bo0[i]; v.w=bg0[i];
        reinterpret_cast<float4*>(g_bias0i)[i] = v; return;
    }
    i -= S_B;
    if (i < S_B){
        float4 v; v.x=bf1[i]; v.y=bi1[i]; v.z=bo1[i]; v.w=bg1[i];
        reinterpret_cast<float4*>(g_bias1i)[i] = v; return;
    }
    i -= S_B;
    // zero state: c0 (32768 f4), c1 (32768 f4), comb1 (65536 f4), barc
    {
        float4 z = make_float4(0.f,0.f,0.f,0.f);
        if (i < 32768){ reinterpret_cast<float4*>(g_c0)[i] = z; return; }
        i -= 32768;
        if (i < 32768){ reinterpret_cast<float4*>(g_c1)[i] = z; return; }
        i -= 32768;
        if (i < 65536){ reinterpret_cast<float4*>(g_comb1)[i] = z; return; }
        i -= 65536;
        if (i == 0) g_barc = 0u;
    }
}

__global__ void build_a0(const int* __restrict__ tokens, const float* __restrict__ emb){
    int idx = blockIdx.x*blockDim.x + threadIdx.x;
    if (idx >= Tt*Bb*1536) return;
    int row = idx / 1536;
    int col = idx - row*1536;
    int t = row >> 7;
    int b = row & 127;
    float v;
    if (col < Ee) v = roundtf(emb[(size_t)tokens[b*Tt + t]*Ee + col]);
    else          v = g_feat[b*Hh + (col - Ee)];
    g_A0[idx] = v;
}

// ---------------- 128x128x16 TF32 GEMM (feat / pre0 / out) ----------------
#define MODE_LEAKY 1
#define MODE_REMAP 4

__global__ __launch_bounds__(256) void gemm128(
    const float* __restrict__ A, int lda, int K,
    const float* __restrict__ W, int ldw,
    const float* __restrict__ bias,
    float* __restrict__ C, int ldc, int N, int mode)
{
    __shared__ __align__(16) float As[4][128][20];
    __shared__ __align__(16) float Ws[4][16][136];

    const int n0 = blockIdx.x * 128;
    const int m0 = blockIdx.y * 128;
    const int tid  = threadIdx.x;
    const int lane = tid & 31, warp = tid >> 5;
    const int wm = warp & 3, wn = warp >> 2;      // 4x2 warps, warp tile 32x64
    const int g  = lane >> 2, tg = lane & 3;

    // gmem->smem coords: 2 float4s each for A and W per stage
    const int ar = tid >> 1,  ac = (tid & 1) * 8;    // A: 128 rows x 16
    const int wr = tid >> 4,  wc = (tid & 15) * 8;   // W: 16 rows x 128
    const bool wp0 = (n0 + wc)     < N;
    const bool wp1 = (n0 + wc + 4) < N;
    const float* asrc = A + (size_t)(m0+ar)*lda + ac;
    const float* wsrc = W + (size_t)wr*ldw + n0 + wc;

    float acc[2][8][4];
    #pragma unroll
    for (int mi=0;mi<2;mi++)
        #pragma unroll
        for (int ni=0;ni<8;ni++)
            #pragma unroll
            for (int j=0;j<4;j++) acc[mi][ni][j]=0.f;

    const int nk = K >> 4;
    #pragma unroll
    for (int s=0; s<3; ++s){
        cp16 (&As[s][ar][ac],   asrc + s*16);
        cp16 (&As[s][ar][ac+4], asrc + s*16 + 4);
        cp16p(&Ws[s][wr][wc],   wp0 ? (wsrc + (size_t)(s*16)*ldw)     : W, wp0);
        cp16p(&Ws[s][wr][wc+4], wp1 ? (wsrc + (size_t)(s*16)*ldw + 4) : W, wp1);
        cp_commit();
    }

    for (int kt=0; kt<nk; ++kt){
        cp_wait2();
        __syncthreads();
        int kn = kt + 3;
        if (kn < nk){
            int sn = kn & 3;
            cp16 (&As[sn][ar][ac],   asrc + kn*16);
            cp16 (&As[sn][ar][ac+4], asrc + kn*16 + 4);
            cp16p(&Ws[sn][wr][wc],   wp0 ? (wsrc + (size_t)(kn*16)*ldw)     : W, wp0);
            cp16p(&Ws[sn][wr][wc+4], wp1 ? (wsrc + (size_t)(kn*16)*ldw + 4) : W, wp1);
        }
        cp_commit();
        const int st = kt & 3;
        #pragma unroll
        for (int kk=0; kk<2; ++kk){
            const int kc = kk*8 + tg;
            uint32_t afr[2][4];
            #pragma unroll
            for (int mi=0; mi<2; ++mi){
                const int rr = wm*32 + mi*16 + g;
                afr[mi][0] = __float_as_uint(As[st][rr  ][kc  ]);
                afr[mi][1] = __float_as_uint(As[st][rr+8][kc  ]);
                afr[mi][2] = __float_as_uint(As[st][rr  ][kc+4]);
                afr[mi][3] = __float_as_uint(As[st][rr+8][kc+4]);
            }
            #pragma unroll
            for (int ni=0; ni<8; ++ni){
                const int nc = wn*64 + ni*8 + g;
                uint32_t b0 = __float_as_uint(Ws[st][kc  ][nc]);
                uint32_t b1 = __float_as_uint(Ws[st][kc+4][nc]);
                #pragma unroll
                for (int mi=0; mi<2; ++mi){
                    asm volatile(
                        "mma.sync.aligned.m16n8k8.row.col.f32.tf32.tf32.f32 "
                        "{%0,%1,%2,%3}, {%4,%5,%6,%7}, {%8,%9}, {%0,%1,%2,%3};\n"
                        : "+f"(acc[mi][ni][0]), "+f"(acc[mi][ni][1]),
                          "+f"(acc[mi][ni][2]), "+f"(acc[mi][ni][3])
                        : "r"(afr[mi][0]), "r"(afr[mi][1]),
                          "r"(afr[mi][2]), "r"(afr[mi][3]), "r"(b0), "r"(b1));
                }
            }
        }
    }

    // epilogue
    #pragma unroll
    for (int mi=0; mi<2; ++mi){
        const int grow0 = m0 + wm*32 + mi*16 + g;
        const int grow1 = grow0 + 8;
        size_t drow0, drow1;
        if (mode & MODE_REMAP){
            drow0 = (size_t)((grow0 & 127)*Tt + (grow0 >> 7));
            drow1 = (size_t)((grow1 & 127)*Tt + (grow1 >> 7));
        } else { drow0 = (size_t)grow0; drow1 = (size_t)grow1; }
        float* C0 = C + drow0*ldc;
        float* C1 = C + drow1*ldc;
        #pragma unroll
        for (int ni=0; ni<8; ++ni){
            const int gcol = n0 + wn*64 + ni*8 + 2*tg;
            if (gcol >= N) continue;
            float v00=acc[mi][ni][0], v01=acc[mi][ni][1];
            float v10=acc[mi][ni][2], v11=acc[mi][ni][3];
            float b0v = bias[gcol], b1v = bias[gcol+1];
            v00+=b0v; v01+=b1v; v10+=b0v; v11+=b1v;
            if (mode & MODE_LEAKY){
                v00 = roundtf(v00 > 0.f ? v00 : 0.01f*v00);
                v01 = roundtf(v01 > 0.f ? v01 : 0.01f*v01);
                v10 = roundtf(v10 > 0.f ? v10 : 0.01f*v10);
                v11 = roundtf(v11 > 0.f ? v11 : 0.01f*v11);
            }
            C0[gcol] = v00; C0[gcol+1] = v01;
            C1[gcol] = v10; C1[gcol+1] = v11;
        }
    }
}

// ---------------- persistent recurrence (unchanged from R4) ----------------
#define NCTA 256u

__device__ __forceinline__ void gridbar(unsigned &ep){
    __syncthreads();
    ep += 1;
    if (threadIdx.x == 0){
        __threadfence();
        atomicAdd(&g_barc, 1u);
        unsigned tgt = ep * NCTA;
        unsigned v;
        do {
            asm volatile("ld.acquire.gpu.u32 %0, [%1];" : "=r"(v) : "l"(&g_barc) : "memory");
        } while (v < tgt);
    }
    __syncthreads();
}

__device__ __forceinline__ void gemm_tile_dev(
    const float* __restrict__ A, int lda,
    const float* __restrict__ W, int ldw,
    int m0, int n0, int kbase, int nk,
    float (&As)[4][64][20], float (&Ws)[4][16][72],
    float acc[4][4])
{
    const int tid  = threadIdx.x;
    const int lane = tid & 31, warp = tid >> 5;
    const int wm = warp & 3, wn = warp >> 2;
    const int g  = lane >> 2, tg = lane & 3;
    const int ar = tid >> 2,  ac = (tid & 3)  * 4;
    const int wr = tid >> 4,  wc = (tid & 15) * 4;
    const float* asrc = A + (size_t)(m0+ar)*lda + kbase + ac;
    const float* wsrc = W + (size_t)(kbase+wr)*ldw + n0 + wc;

    #pragma unroll
    for (int i=0;i<4;i++){
        #pragma unroll
        for (int j=0;j<4;j++) acc[i][j]=0.f;
    }

    #pragma unroll
    for (int s=0; s<3; ++s){
        cp16(&As[s][ar][ac], asrc + s*16);
        cp16(&Ws[s][wr][wc], wsrc + (size_t)(s*16)*ldw);
        cp_commit();
    }
    for (int kt=0; kt<nk; ++kt){
        cp_wait2();
        __syncthreads();
        int kn = kt + 3;
        if (kn < nk){
            int sn = kn & 3;
            cp16(&As[sn][ar][ac], asrc + kn*16);
            cp16(&Ws[sn][wr][wc], wsrc + (size_t)(kn*16)*ldw);
        }
        cp_commit();
        const int st = kt & 3;
        const int rr = wm*16 + g;
        #pragma unroll
        for (int kk=0; kk<2; ++kk){
            const int kc = kk*8 + tg;
            uint32_t a0 = __float_as_uint(As[st][rr  ][kc  ]);
            uint32_t a1 = __float_as_uint(As[st][rr+8][kc  ]);
            uint32_t a2 = __float_as_uint(As[st][rr  ][kc+4]);
            uint32_t a3 = __float_as_uint(As[st][rr+8][kc+4]);
            #pragma unroll
            for (int ni=0; ni<4; ++ni){
                const int nc = wn*32 + ni*8 + g;
                uint32_t b0 = __float_as_uint(Ws[st][kc  ][nc]);
                uint32_t b1 = __float_as_uint(Ws[st][kc+4][nc]);
                asm volatile(
                    "mma.sync.aligned.m16n8k8.row.col.f32.tf32.tf32.f32 "
                    "{%0,%1,%2,%3}, {%4,%5,%6,%7}, {%8,%9}, {%0,%1,%2,%3};\n"
                    : "+f"(acc[ni][0]), "+f"(acc[ni][1]),
                      "+f"(acc[ni][2]), "+f"(acc[ni][3])
                    : "r"(a0), "r"(a1), "r"(a2), "r"(a3), "r"(b0), "r"(b1));
            }
        }
    }
    cp_wait0();
    __syncthreads();
}

__device__ __forceinline__ void store_partial(float acc[4][4], int tile,
                                              int wm, int wn, int g, int tg)
{
    float* gp = g_part + (size_t)tile*4096;
    const int lr0 = wm*16 + g, lr1 = lr0 + 8;
    #pragma unroll
    for (int ni=0; ni<4; ++ni){
        const int lc = wn*32 + ni*8 + 2*tg;
        gp[lr0*64 + lc]   = acc[ni][0];
        gp[lr0*64 + lc+1] = acc[ni][1];
        gp[lr1*64 + lc]   = acc[ni][2];
        gp[lr1*64 + lc+1] = acc[ni][3];
    }
}

__device__ __forceinline__ void lstm_epi(float acc[4][4], int tile, int t,
    const float* rowext, const float* colext,
    float* cbuf, int hoff, bool write_hs,
    int m0, int n0, int nb, int wm, int wn, int g, int tg)
{
    const float* gp = g_part + (size_t)tile*4096;
    const int lr0 = wm*16 + g, lr1 = lr0 + 8;
    const int grow0 = m0 + lr0, grow1 = m0 + lr1;
    #pragma unroll
    for (int ni=0; ni<4; ++ni){
        const int lc = wn*32 + ni*8 + 2*tg;
        const int gcol = n0 + lc;
        float v00 = acc[ni][0] + gp[lr0*64 + lc];
        float v01 = acc[ni][1] + gp[lr0*64 + lc+1];
        float v10 = acc[ni][2] + gp[lr1*64 + lc];
        float v11 = acc[ni][3] + gp[lr1*64 + lc+1];
        if (rowext){
            v00 += rowext[(size_t)grow0*4096 + gcol];
            v01 += rowext[(size_t)grow0*4096 + gcol+1];
            v10 += rowext[(size_t)grow1*4096 + gcol];
            v11 += rowext[(size_t)grow1*4096 + gcol+1];
        } else {
            float b0 = colext[gcol], b1 = colext[gcol+1];
            v00+=b0; v01+=b1; v10+=b0; v11+=b1;
        }
        float p00 = __shfl_xor_sync(0xffffffffu, v00, 1);
        float p01 = __shfl_xor_sync(0xffffffffu, v01, 1);
        float p10 = __shfl_xor_sync(0xffffffffu, v10, 1);
        float p11 = __shfl_xor_sync(0xffffffffu, v11, 1);
        if ((tg & 1) == 0){
            const int h = nb*16 + wn*8 + ni*2 + (tg >> 1);
            {
                float f = sigf(v00), ii = sigf(v01);
                float o = sigf(p00), gg = tanhf(p01);
                float c = f*cbuf[grow0*1024 + h] + ii*gg;
                cbuf[grow0*1024 + h] = c;
                float hn = roundtf(o * tanhf(c));
                g_comb1[grow0*2048 + hoff + h] = hn;
                if (write_hs) g_hs[(size_t)t*(Bb*Hh) + grow0*1024 + h] = hn;
            }
            {
                float f = sigf(v10), ii = sigf(v11);
                float o = sigf(p10), gg = tanhf(p11);
                float c = f*cbuf[grow1*1024 + h] + ii*gg;
                cbuf[grow1*1024 + h] = c;
                float hn = roundtf(o * tanhf(c));
                g_comb1[grow1*2048 + hoff + h] = hn;
                if (write_hs) g_hs[(size_t)t*(Bb*Hh) + grow1*1024 + h] = hn;
            }
        }
    }
}

__global__ __launch_bounds__(256, 2) void lstm_persistent()
{
    __shared__ __align__(16) float As[4][64][20];
    __shared__ __align__(16) float Ws[4][16][72];

    const int cta  = blockIdx.x;
    const int ks   = cta & 1;
    const int tile = cta >> 1;
    const int mb   = tile & 1, nb = tile >> 1;
    const int m0   = mb*64,   n0 = nb*64;
    const int tid  = threadIdx.x;
    const int lane = tid & 31, warp = tid >> 5;
    const int wm = warp & 3, wn = warp >> 2;
    const int g  = lane >> 2, tg = lane & 3;

    const float* Wrec0 = g_wbuf + OF_W0I + (size_t)1536*4096;
    const float* W1    = g_wbuf + OF_W1I;

    unsigned ep = 0;
    float acc[4][4];

    for (int t = 0; t < Tt; ++t){
        gemm_tile_dev(g_comb1, 2048, Wrec0, 4096, m0, n0, ks*512, 32, As, Ws, acc);
        if (ks == 1) store_partial(acc, tile, wm, wn, g, tg);
        gridbar(ep);
        if (ks == 0)
            lstm_epi(acc, tile, t, g_pre0 + (size_t)t*(Bb*4096), nullptr,
                     g_c0, 0, false, m0, n0, nb, wm, wn, g, tg);
        gridbar(ep);
        gemm_tile_dev(g_comb1, 2048, W1, 4096, m0, n0, ks*1024, 64, As, Ws, acc);
        if (ks == 1) store_partial(acc, tile, wm, wn, g, tg);
        gridbar(ep);
        if (ks == 0)
            lstm_epi(acc, tile, t, nullptr, g_bias1i,
                     g_c1, 1024, true, m0, n0, nb, wm, wn, g, tg);
        gridbar(ep);
    }
}

// ---------------- host orchestration ----------------
extern "C" void kernel_launch(void* const* d_in, const int* in_sizes, int n_in,
                              void* d_out, int out_size)
{
    const int*   tokens    = (const int*)  d_in[0];
    const float* features  = (const float*)d_in[1];
    const float* embedding = (const float*)d_in[2];
    const float* Wp  = (const float*)d_in[3];
    const float* bp  = (const float*)d_in[4];
    const float* Wf0 = (const float*)d_in[5];  const float* bf0 = (const float*)d_in[6];
    const float* Wi0 = (const float*)d_in[7];  const float* bi0 = (const float*)d_in[8];
    const float* Wo0 = (const float*)d_in[9];  const float* bo0 = (const float*)d_in[10];
    const float* Wg0 = (const float*)d_in[11]; const float* bg0 = (const float*)d_in[12];
    const float* Wf1 = (const float*)d_in[13]; const float* bf1 = (const float*)d_in[14];
    const float* Wi1 = (const float*)d_in[15]; const float* bi1 = (const float*)d_in[16];
    const float* Wo1 = (const float*)d_in[17]; const float* bo1 = (const float*)d_in[18];
    const float* Wg1 = (const float*)d_in[19]; const float* bg1 = (const float*)d_in[20];
    const float* Wout = (const float*)d_in[21];
    const float* bout = (const float*)d_in[22];
    float* out = (float*)d_out;

    float *wb, *featin, *feat, *a0, *pre0, *hs, *b0i;
    cudaGetSymbolAddress((void**)&wb,     g_wbuf);
    cudaGetSymbolAddress((void**)&featin, g_featin);
    cudaGetSymbolAddress((void**)&feat,   g_feat);
    cudaGetSymbolAddress((void**)&a0,     g_A0);
    cudaGetSymbolAddress((void**)&pre0,   g_pre0);
    cudaGetSymbolAddress((void**)&hs,     g_hs);
    cudaGetSymbolAddress((void**)&b0i,    g_bias0i);

    // 1) convert + pack + zero (single launch)
    cvt_all<<<(CVT_TOTAL + 255)/256, 256>>>(features, Wp, Wout,
        Wf0, Wi0, Wo0, Wg0, Wf1, Wi1, Wo1, Wg1,
        bf0, bi0, bo0, bg0, bf1, bi1, bo1, bg1);

    // 2) feature projection: [128,1024]
    gemm128<<<dim3(8,1), 256>>>(featin, Ff, Ff,
        wb + OF_WP, Hh, bp, feat, Hh, Hh, MODE_LEAKY);

    // 3) A0 = [emb_t | feat]
    build_a0<<<(Tt*Bb*1536 + 255)/256, 256>>>(tokens, embedding);

    // 4) pre0 = A0 @ W0i[0:1536,:] + bias0i   <-- profiled slot
    gemm128<<<dim3(32,25), 256>>>(a0, 1536, 1536,
        wb + OF_W0I, 4096, b0i, pre0, 4096, 4096, 0);

    // 5) persistent 25-step recurrence
    lstm_persistent<<<NCTA, 256>>>();

    // 6) logits = hs @ Wout + bout, remap to [B,T,V]
    gemm128<<<dim3(79,25), 256>>>(hs, Hh, Hh,
        wb + OF_WOUT, Vv, bout, out, Vv, Vv, MODE_REMAP);
}

// round 7
// speedup vs baseline: 1.0502x; 1.0299x over previous
#include <cuda_runtime.h>
#include <cstdint>
#include <math.h>

#define Bb 128
#define Tt 25
#define Ee 512
#define Hh 1024
#define Vv 10000
#define Ff 2048

// ---------------- device scratch ----------------
__device__ float g_wbuf[36331520];     // tf32-rounded weights + embedding
__device__ float g_featin[Bb*Ff];
__device__ float g_feat[Bb*Hh];
__device__ float g_prefeat[Bb*4096];   // feat @ W0i[512:1536] + bias0i
__device__ float g_pre0[Tt*Bb*4096];   // full input-part of layer0 gates
__device__ float g_c0[Bb*Hh];
__device__ float g_c1[Bb*Hh];
__device__ float g_comb1[Bb*2048];     // [h0 | h1]
__device__ float g_hs[Tt*Bb*Hh];
__device__ float g_part[128*4096];     // k-split partial tiles
__device__ float g_bias0i[4096];
__device__ float g_bias1i[4096];
__device__ unsigned g_bgrp[8*64];      // persistent barrier: 8 group counters, 256B stride
__device__ unsigned g_barc;            // persistent barrier root
__device__ unsigned g_hbar;            // head kernel barrier

// wbuf offsets (floats)
#define OF_WP   0
#define OF_W0I  2097152      /* 2560x4096 interleaved */
#define OF_W1I  12582912     /* 2048x4096 interleaved */
#define OF_WOUT 20971520     /* 1024x10000 -> ends at 31211520 */
#define OF_EMB  31211520     /* 10000x512 rounded embedding */

__device__ __forceinline__ uint32_t f2tf(float x){
    uint32_t u; asm("cvt.rna.tf32.f32 %0, %1;" : "=r"(u) : "f"(x)); return u;
}
__device__ __forceinline__ float roundtf(float x){ return __uint_as_float(f2tf(x)); }
__device__ __forceinline__ float sigf(float x){ return 1.0f/(1.0f + expf(-x)); }

__device__ __forceinline__ void cp16(float* sdst, const float* gsrc){
    uint32_t s = (uint32_t)__cvta_generic_to_shared(sdst);
    asm volatile("cp.async.cg.shared.global [%0], [%1], 16;\n" :: "r"(s), "l"(gsrc));
}
__device__ __forceinline__ void cp16p(float* sdst, const float* gsrc, bool pred){
    uint32_t s = (uint32_t)__cvta_generic_to_shared(sdst);
    int sz = pred ? 16 : 0;
    asm volatile("cp.async.cg.shared.global [%0], [%1], 16, %2;\n" :: "r"(s), "l"(gsrc), "r"(sz));
}
__device__ __forceinline__ void cp_commit(){ asm volatile("cp.async.commit_group;\n"); }
__device__ __forceinline__ void cp_wait2(){ asm volatile("cp.async.wait_group 2;\n"); }
__device__ __forceinline__ void cp_wait0(){ asm volatile("cp.async.wait_group 0;\n"); }

// ---------------- one-shot convert / pack / zero kernel ----------------
#define S_FEAT 65536
#define S_WP   524288
#define S_WOUT 2560000
#define S_EMB  1280000
#define S_W0I  2621440
#define S_W1I  2097152
#define S_B    1024
#define S_Z    (32768+32768+65536+3+512)
#define CVT_TOTAL (S_FEAT+S_WP+S_WOUT+S_EMB+S_W0I+S_W1I+2*S_B+S_Z)

__global__ void cvt_all(
    const float* __restrict__ features, const float* __restrict__ Wp,
    const float* __restrict__ Wout, const float* __restrict__ emb,
    const float* __restrict__ Wf0, const float* __restrict__ Wi0,
    const float* __restrict__ Wo0, const float* __restrict__ Wg0,
    const float* __restrict__ Wf1, const float* __restrict__ Wi1,
    const float* __restrict__ Wo1, const float* __restrict__ Wg1,
    const float* __restrict__ bf0, const float* __restrict__ bi0,
    const float* __restrict__ bo0, const float* __restrict__ bg0,
    const float* __restrict__ bf1, const float* __restrict__ bi1,
    const float* __restrict__ bo1, const float* __restrict__ bg1)
{
    int i = blockIdx.x*blockDim.x + threadIdx.x;
    if (i >= CVT_TOTAL) return;
    if (i < S_FEAT){
        float4 v = reinterpret_cast<const float4*>(features)[i];
        v.x=roundtf(v.x); v.y=roundtf(v.y); v.z=roundtf(v.z); v.w=roundtf(v.w);
        reinterpret_cast<float4*>(g_featin)[i] = v; return;
    }
    i -= S_FEAT;
    if (i < S_WP){
        float4 v = reinterpret_cast<const float4*>(Wp)[i];
        v.x=roundtf(v.x); v.y=roundtf(v.y); v.z=roundtf(v.z); v.w=roundtf(v.w);
        reinterpret_cast<float4*>(g_wbuf + OF_WP)[i] = v; return;
    }
    i -= S_WP;
    if (i < S_WOUT){
        float4 v = reinterpret_cast<const float4*>(Wout)[i];
        v.x=roundtf(v.x); v.y=roundtf(v.y); v.z=roundtf(v.z); v.w=roundtf(v.w);
        reinterpret_cast<float4*>(g_wbuf + OF_WOUT)[i] = v; return;
    }
    i -= S_WOUT;
    if (i < S_EMB){
        float4 v = reinterpret_cast<const float4*>(emb)[i];
        v.x=roundtf(v.x); v.y=roundtf(v.y); v.z=roundtf(v.z); v.w=roundtf(v.w);
        reinterpret_cast<float4*>(g_wbuf + OF_EMB)[i] = v; return;
    }
    i -= S_EMB;
    if (i < S_W0I){
        int k = i >> 10, h = i & 1023;
        int s = k*1024 + h;
        float4 v;
        v.x = roundtf(Wf0[s]); v.y = roundtf(Wi0[s]);
        v.z = roundtf(Wo0[s]); v.w = roundtf(Wg0[s]);
        reinterpret_cast<float4*>(g_wbuf + OF_W0I)[(size_t)k*1024 + h] = v; return;
    }
    i -= S_W0I;
    if (i < S_W1I){
        int k = i >> 10, h = i & 1023;
        int s = k*1024 + h;
        float4 v;
        v.x = roundtf(Wf1[s]); v.y = roundtf(Wi1[s]);
        v.z = roundtf(Wo1[s]); v.w = roundtf(Wg1[s]);
        reinterpret_cast<float4*>(g_wbuf + OF_W1I)[(size_t)k*1024 + h] = v; return;
    }
    i -= S_W1I;
    if (i < S_B){
        float4 v; v.x=bf0[i]; v.y=bi0[i]; v.z=bo0[i]; v.w=bg0[i];
        reinterpret_cast<float4*>(g_bias0i)[i] = v; return;
    }
    i -= S_B;
    if (i < S_B){
        float4 v; v.x=bf1[i]; v.y=bi1[i]; v.z=bo1[i]; v.w=bg1[i];
        reinterpret_cast<float4*>(g_bias1i)[i] = v; return;
    }
    i -= S_B;
    {
        float4 z = make_float4(0.f,0.f,0.f,0.f);
        if (i < 32768){ reinterpret_cast<float4*>(g_c0)[i] = z; return; }
        i -= 32768;
        if (i < 32768){ reinterpret_cast<float4*>(g_c1)[i] = z; return; }
        i -= 32768;
        if (i < 65536){ reinterpret_cast<float4*>(g_comb1)[i] = z; return; }
        i -= 65536;
        if (i == 0){ g_barc = 0u; return; }
        if (i == 1){ g_hbar = 0u; return; }
        if (i == 2) return;
        g_bgrp[i-3] = 0u;
    }
}

// ---------------- 128x128x16 TF32 GEMM body ----------------
#define MODE_LEAKY 1
#define MODE_REMAP 4

struct SmemGemm {
    float As[4][128][20];
    float Ws[4][16][136];
};

__device__ __forceinline__ void gemm128_body(
    const float* __restrict__ A, int lda, int K,
    const float* __restrict__ W, int ldw,
    const float* __restrict__ bias, const float* __restrict__ rowext,
    float* __restrict__ C, int ldc, int N, int mode,
    int n0, int m0,
    const int* __restrict__ gtok, const float* __restrict__ embW,
    SmemGemm& s)
{
    const int tid  = threadIdx.x;
    const int lane = tid & 31, warp = tid >> 5;
    const int wm = warp & 3, wn = warp >> 2;      // warp tile 32x64
    const int g  = lane >> 2, tg = lane & 3;

    const int ar = tid >> 1,  ac = (tid & 1) * 8;
    const int wr = tid >> 4,  wc = (tid & 15) * 8;
    const bool wp0 = (n0 + wc)     < N;
    const bool wp1 = (n0 + wc + 4) < N;
    const float* asrc;
    if (gtok){
        int t = m0 >> 7;
        int tok = gtok[ar*Tt + t];
        asrc = embW + (size_t)tok*Ee + ac;
    } else {
        asrc = A + (size_t)(m0+ar)*lda + ac;
    }
    const float* wsrc = W + (size_t)wr*ldw + n0 + wc;

    float acc[2][8][4];
    #pragma unroll
    for (int mi=0;mi<2;mi++)
        #pragma unroll
        for (int ni=0;ni<8;ni++)
            #pragma unroll
            for (int j=0;j<4;j++) acc[mi][ni][j]=0.f;

    const int nk = K >> 4;
    #pragma unroll
    for (int st2=0; st2<3; ++st2){
        cp16 (&s.As[st2][ar][ac],   asrc + st2*16);
        cp16 (&s.As[st2][ar][ac+4], asrc + st2*16 + 4);
        cp16p(&s.Ws[st2][wr][wc],   wp0 ? (wsrc + (size_t)(st2*16)*ldw)     : W, wp0);
        cp16p(&s.Ws[st2][wr][wc+4], wp1 ? (wsrc + (size_t)(st2*16)*ldw + 4) : W, wp1);
        cp_commit();
    }

    for (int kt=0; kt<nk; ++kt){
        cp_wait2();
        __syncthreads();
        int kn = kt + 3;
        if (kn < nk){
            int sn = kn & 3;
            cp16 (&s.As[sn][ar][ac],   asrc + kn*16);
            cp16 (&s.As[sn][ar][ac+4], asrc + kn*16 + 4);
            cp16p(&s.Ws[sn][wr][wc],   wp0 ? (wsrc + (size_t)(kn*16)*ldw)     : W, wp0);
            cp16p(&s.Ws[sn][wr][wc+4], wp1 ? (wsrc + (size_t)(kn*16)*ldw + 4) : W, wp1);
        }
        cp_commit();
        const int st = kt & 3;
        #pragma unroll
        for (int kk=0; kk<2; ++kk){
            const int kc = kk*8 + tg;
            uint32_t afr[2][4];
            #pragma unroll
            for (int mi=0; mi<2; ++mi){
                const int rr = wm*32 + mi*16 + g;
                afr[mi][0] = __float_as_uint(s.As[st][rr  ][kc  ]);
                afr[mi][1] = __float_as_uint(s.As[st][rr+8][kc  ]);
                afr[mi][2] = __float_as_uint(s.As[st][rr  ][kc+4]);
                afr[mi][3] = __float_as_uint(s.As[st][rr+8][kc+4]);
            }
            #pragma unroll
            for (int ni=0; ni<8; ++ni){
                const int nc = wn*64 + ni*8 + g;
                uint32_t b0 = __float_as_uint(s.Ws[st][kc  ][nc]);
                uint32_t b1 = __float_as_uint(s.Ws[st][kc+4][nc]);
                #pragma unroll
                for (int mi=0; mi<2; ++mi){
                    asm volatile(
                        "mma.sync.aligned.m16n8k8.row.col.f32.tf32.tf32.f32 "
                        "{%0,%1,%2,%3}, {%4,%5,%6,%7}, {%8,%9}, {%0,%1,%2,%3};\n"
                        : "+f"(acc[mi][ni][0]), "+f"(acc[mi][ni][1]),
                          "+f"(acc[mi][ni][2]), "+f"(acc[mi][ni][3])
                        : "r"(afr[mi][0]), "r"(afr[mi][1]),
                          "r"(afr[mi][2]), "r"(afr[mi][3]), "r"(b0), "r"(b1));
                }
            }
        }
    }
    cp_wait0();
    __syncthreads();

    #pragma unroll
    for (int mi=0; mi<2; ++mi){
        const int grow0 = m0 + wm*32 + mi*16 + g;
        const int grow1 = grow0 + 8;
        size_t drow0, drow1;
        if (mode & MODE_REMAP){
            drow0 = (size_t)((grow0 & 127)*Tt + (grow0 >> 7));
            drow1 = (size_t)((grow1 & 127)*Tt + (grow1 >> 7));
        } else { drow0 = (size_t)grow0; drow1 = (size_t)grow1; }
        float* C0 = C + drow0*ldc;
        float* C1 = C + drow1*ldc;
        #pragma unroll
        for (int ni=0; ni<8; ++ni){
            const int gcol = n0 + wn*64 + ni*8 + 2*tg;
            if (gcol >= N) continue;
            float v00=acc[mi][ni][0], v01=acc[mi][ni][1];
            float v10=acc[mi][ni][2], v11=acc[mi][ni][3];
            if (bias){
                float b0v = bias[gcol], b1v = bias[gcol+1];
                v00+=b0v; v01+=b1v; v10+=b0v; v11+=b1v;
            }
            if (rowext){
                const float* r0 = rowext + (size_t)(grow0 & 127)*4096;
                const float* r1 = rowext + (size_t)(grow1 & 127)*4096;
                v00 += r0[gcol]; v01 += r0[gcol+1];
                v10 += r1[gcol]; v11 += r1[gcol+1];
            }
            if (mode & MODE_LEAKY){
                v00 = roundtf(v00 > 0.f ? v00 : 0.01f*v00);
                v01 = roundtf(v01 > 0.f ? v01 : 0.01f*v01);
                v10 = roundtf(v10 > 0.f ? v10 : 0.01f*v10);
                v11 = roundtf(v11 > 0.f ? v11 : 0.01f*v11);
            }
            C0[gcol] = v00; C0[gcol+1] = v01;
            C1[gcol] = v10; C1[gcol+1] = v11;
        }
    }
}

__global__ __launch_bounds__(256) void gemm128k(
    const float* __restrict__ A, int lda, int K,
    const float* __restrict__ W, int ldw,
    const float* __restrict__ bias, const float* __restrict__ rowext,
    float* __restrict__ C, int ldc, int N, int mode,
    const int* __restrict__ gtok, const float* __restrict__ embW)
{
    __shared__ SmemGemm s;
    gemm128_body(A, lda, K, W, ldw, bias, rowext, C, ldc, N, mode,
                 blockIdx.x*128, blockIdx.y*128, gtok, embW, s);
}

// head: phase A (CTAs 0-7) feat = leaky(featin@Wp+bp); barrier;
//       phase B (CTAs 8-39) prefeat = feat@W0i[512:1536] + bias0i
__global__ __launch_bounds__(256) void head_kernel(const float* __restrict__ bp)
{
    __shared__ SmemGemm s;
    const int cta = blockIdx.x;
    if (cta < 8){
        gemm128_body(g_featin, Ff, Ff, g_wbuf + OF_WP, Hh, bp, nullptr,
                     g_feat, Hh, Hh, MODE_LEAKY, cta*128, 0, nullptr, nullptr, s);
    }
    __syncthreads();
    if (threadIdx.x == 0){
        __threadfence();
        atomicAdd(&g_hbar, 1u);
        unsigned v;
        do {
            asm volatile("ld.acquire.gpu.u32 %0, [%1];" : "=r"(v) : "l"(&g_hbar) : "memory");
        } while (v < 40u);
    }
    __syncthreads();
    if (cta >= 8){
        gemm128_body(g_feat, Hh, Hh, g_wbuf + OF_W0I + (size_t)512*4096, 4096,
                     g_bias0i, nullptr, g_prefeat, 4096, 4096, 0,
                     (cta-8)*128, 0, nullptr, nullptr, s);
    }
}

// ---------------- persistent recurrence ----------------
#define NCTA 256u

__device__ __forceinline__ void gridbar(unsigned &ep, int cta){
    __syncthreads();
    ep += 1;
    if (threadIdx.x == 0){
        __threadfence();
        const int grp = cta >> 5;                 // 8 groups of 32
        unsigned* gc = &g_bgrp[grp*64];
        atomicAdd(gc, 1u);
        unsigned v;
        if ((cta & 31) == 0){
            do {
                asm volatile("ld.acquire.gpu.u32 %0, [%1];" : "=r"(v) : "l"(gc) : "memory");
            } while (v < ep*32u);
            __threadfence();   // release: carry group's writes into the root add
            atomicAdd(&g_barc, 1u);
        }
        do {
            asm volatile("ld.acquire.gpu.u32 %0, [%1];" : "=r"(v) : "l"(&g_barc) : "memory");
        } while (v < ep*8u);
    }
    __syncthreads();
}

__device__ __forceinline__ void gemm_tile_dev(
    const float* __restrict__ A, int lda,
    const float* __restrict__ W, int ldw,
    int m0, int n0, int kbase, int nk,
    float (&As)[4][64][20], float (&Ws)[4][16][72],
    float acc[4][4])
{
    const int tid  = threadIdx.x;
    const int lane = tid & 31, warp = tid >> 5;
    const int wm = warp & 3, wn = warp >> 2;
    const int g  = lane >> 2, tg = lane & 3;
    const int ar = tid >> 2,  ac = (tid & 3)  * 4;
    const int wr = tid >> 4,  wc = (tid & 15) * 4;
    const float* asrc = A + (size_t)(m0+ar)*lda + kbase + ac;
    const float* wsrc = W + (size_t)(kbase+wr)*ldw + n0 + wc;

    #pragma unroll
    for (int i=0;i<4;i++){
        #pragma unroll
        for (int j=0;j<4;j++) acc[i][j]=0.f;
    }

    #pragma unroll
    for (int st2=0; st2<3; ++st2){
        cp16(&As[st2][ar][ac], asrc + st2*16);
        cp16(&Ws[st2][wr][wc], wsrc + (size_t)(st2*16)*ldw);
        cp_commit();
    }
    for (int kt=0; kt<nk; ++kt){
        cp_wait2();
        __syncthreads();
        int kn = kt + 3;
        if (kn < nk){
            int sn = kn & 3;
            cp16(&As[sn][ar][ac], asrc + kn*16);
            cp16(&Ws[sn][wr][wc], wsrc + (size_t)(kn*16)*ldw);
        }
        cp_commit();
        const int st = kt & 3;
        const int rr = wm*16 + g;
        #pragma unroll
        for (int kk=0; kk<2; ++kk){
            const int kc = kk*8 + tg;
            uint32_t a0 = __float_as_uint(As[st][rr  ][kc  ]);
            uint32_t a1 = __float_as_uint(As[st][rr+8][kc  ]);
            uint32_t a2 = __float_as_uint(As[st][rr  ][kc+4]);
            uint32_t a3 = __float_as_uint(As[st][rr+8][kc+4]);
            #pragma unroll
            for (int ni=0; ni<4; ++ni){
                const int nc = wn*32 + ni*8 + g;
                uint32_t b0 = __float_as_uint(Ws[st][kc  ][nc]);
                uint32_t b1 = __float_as_uint(Ws[st][kc+4][nc]);
                asm volatile(
                    "mma.sync.aligned.m16n8k8.row.col.f32.tf32.tf32.f32 "
                    "{%0,%1,%2,%3}, {%4,%5,%6,%7}, {%8,%9}, {%0,%1,%2,%3};\n"
                    : "+f"(acc[ni][0]), "+f"(acc[ni][1]),
                      "+f"(acc[ni][2]), "+f"(acc[ni][3])
                    : "r"(a0), "r"(a1), "r"(a2), "r"(a3), "r"(b0), "r"(b1));
            }
        }
    }
    cp_wait0();
    __syncthreads();
}

__device__ __forceinline__ void store_partial(float acc[4][4], int tile,
                                              int wm, int wn, int g, int tg)
{
    float* gp = g_part + (size_t)tile*4096;
    const int lr0 = wm*16 + g, lr1 = lr0 + 8;
    #pragma unroll
    for (int ni=0; ni<4; ++ni){
        const int lc = wn*32 + ni*8 + 2*tg;
        gp[lr0*64 + lc]   = acc[ni][0];
        gp[lr0*64 + lc+1] = acc[ni][1];
        gp[lr1*64 + lc]   = acc[ni][2];
        gp[lr1*64 + lc+1] = acc[ni][3];
    }
}

__device__ __forceinline__ void lstm_epi(float acc[4][4], int tile, int t,
    const float* rowext, const float* colext,
    float* cbuf, int hoff, bool write_hs,
    int m0, int n0, int nb, int wm, int wn, int g, int tg)
{
    const float* gp = g_part + (size_t)tile*4096;
    const int lr0 = wm*16 + g, lr1 = lr0 + 8;
    const int grow0 = m0 + lr0, grow1 = m0 + lr1;
    #pragma unroll
    for (int ni=0; ni<4; ++ni){
        const int lc = wn*32 + ni*8 + 2*tg;
        const int gcol = n0 + lc;
        float v00 = acc[ni][0] + gp[lr0*64 + lc];
        float v01 = acc[ni][1] + gp[lr0*64 + lc+1];
        float v10 = acc[ni][2] + gp[lr1*64 + lc];
        float v11 = acc[ni][3] + gp[lr1*64 + lc+1];
        if (rowext){
            v00 += rowext[(size_t)grow0*4096 + gcol];
            v01 += rowext[(size_t)grow0*4096 + gcol+1];
            v10 += rowext[(size_t)grow1*4096 + gcol];
            v11 += rowext[(size_t)grow1*4096 + gcol+1];
        } else {
            float b0 = colext[gcol], b1 = colext[gcol+1];
            v00+=b0; v01+=b1; v10+=b0; v11+=b1;
        }
        float p00 = __shfl_xor_sync(0xffffffffu, v00, 1);
        float p01 = __shfl_xor_sync(0xffffffffu, v01, 1);
        float p10 = __shfl_xor_sync(0xffffffffu, v10, 1);
        float p11 = __shfl_xor_sync(0xffffffffu, v11, 1);
        if ((tg & 1) == 0){
            const int h = nb*16 + wn*8 + ni*2 + (tg >> 1);
            {
                float f = sigf(v00), ii = sigf(v01);
                float o = sigf(p00), gg = tanhf(p01);
                float c = f*cbuf[grow0*1024 + h] + ii*gg;
                cbuf[grow0*1024 + h] = c;
                float hn = roundtf(o * tanhf(c));
                g_comb1[grow0*2048 + hoff + h] = hn;
                if (write_hs) g_hs[(size_t)t*(Bb*Hh) + grow0*1024 + h] = hn;
            }
            {
                float f = sigf(v10), ii = sigf(v11);
                float o = sigf(p10), gg = tanhf(p11);
                float c = f*cbuf[grow1*1024 + h] + ii*gg;
                cbuf[grow1*1024 + h] = c;
                float hn = roundtf(o * tanhf(c));
                g_comb1[grow1*2048 + hoff + h] = hn;
                if (write_hs) g_hs[(size_t)t*(Bb*Hh) + grow1*1024 + h] = hn;
            }
        }
    }
}

__global__ __launch_bounds__(256, 2) void lstm_persistent()
{
    __shared__ __align__(16) float As[4][64][20];
    __shared__ __align__(16) float Ws[4][16][72];

    const int cta  = blockIdx.x;
    const int ks   = cta & 1;
    const int tile = cta >> 1;
    const int mb   = tile & 1, nb = tile >> 1;
    const int m0   = mb*64,   n0 = nb*64;
    const int tid  = threadIdx.x;
    const int lane = tid & 31, warp = tid >> 5;
    const int wm = warp & 3, wn = warp >> 2;
    const int g  = lane >> 2, tg = lane & 3;

    const float* Wrec0 = g_wbuf + OF_W0I + (size_t)1536*4096;
    const float* W1    = g_wbuf + OF_W1I;

    unsigned ep = 0;
    float acc[4][4];

    for (int t = 0; t < Tt; ++t){
        gemm_tile_dev(g_comb1, 2048, Wrec0, 4096, m0, n0, ks*512, 32, As, Ws, acc);
        if (ks == 1) store_partial(acc, tile, wm, wn, g, tg);
        gridbar(ep, cta);
        if (ks == 0)
            lstm_epi(acc, tile, t, g_pre0 + (size_t)t*(Bb*4096), nullptr,
                     g_c0, 0, false, m0, n0, nb, wm, wn, g, tg);
        gridbar(ep, cta);
        gemm_tile_dev(g_comb1, 2048, W1, 4096, m0, n0, ks*1024, 64, As, Ws, acc);
        if (ks == 1) store_partial(acc, tile, wm, wn, g, tg);
        gridbar(ep, cta);
        if (ks == 0)
            lstm_epi(acc, tile, t, nullptr, g_bias1i,
                     g_c1, 1024, true, m0, n0, nb, wm, wn, g, tg);
        gridbar(ep, cta);
    }
}

// ---------------- host orchestration ----------------
extern "C" void kernel_launch(void* const* d_in, const int* in_sizes, int n_in,
                              void* d_out, int out_size)
{
    const int*   tokens    = (const int*)  d_in[0];
    const float* features  = (const float*)d_in[1];
    const float* embedding = (const float*)d_in[2];
    const float* Wp  = (const float*)d_in[3];
    const float* bp  = (const float*)d_in[4];
    const float* Wf0 = (const float*)d_in[5];  const float* bf0 = (const float*)d_in[6];
    const float* Wi0 = (const float*)d_in[7];  const float* bi0 = (const float*)d_in[8];
    const float* Wo0 = (const float*)d_in[9];  const float* bo0 = (const float*)d_in[10];
    const float* Wg0 = (const float*)d_in[11]; const float* bg0 = (const float*)d_in[12];
    const float* Wf1 = (const float*)d_in[13]; const float* bf1 = (const float*)d_in[14];
    const float* Wi1 = (const float*)d_in[15]; const float* bi1 = (const float*)d_in[16];
    const float* Wo1 = (const float*)d_in[17]; const float* bo1 = (const float*)d_in[18];
    const float* Wg1 = (const float*)d_in[19]; const float* bg1 = (const float*)d_in[20];
    const float* Wout = (const float*)d_in[21];
    const float* bout = (const float*)d_in[22];
    float* out = (float*)d_out;

    float *wb, *pre0, *hs, *prefeat;
    cudaGetSymbolAddress((void**)&wb,      g_wbuf);
    cudaGetSymbolAddress((void**)&pre0,    g_pre0);
    cudaGetSymbolAddress((void**)&hs,      g_hs);
    cudaGetSymbolAddress((void**)&prefeat, g_prefeat);

    // 1) convert + pack + zero (single launch)
    cvt_all<<<(CVT_TOTAL + 255)/256, 256>>>(features, Wp, Wout, embedding,
        Wf0, Wi0, Wo0, Wg0, Wf1, Wi1, Wo1, Wg1,
        bf0, bi0, bo0, bg0, bf1, bi1, bo1, bg1);

    // 2) head: feat projection + prefeat (fused, internal barrier)
    head_kernel<<<40, 256>>>(bp);

    // 3) pre0 = gather(emb) @ W0i[0:512,:] + prefeat[b]   (K=512)
    gemm128k<<<dim3(32,25), 256>>>(nullptr, 0, 512,
        wb + OF_W0I, 4096, nullptr, prefeat,
        pre0, 4096, 4096, 0, tokens, wb + OF_EMB);

    // 4) persistent 25-step recurrence   <-- profiled slot
    lstm_persistent<<<NCTA, 256>>>();

    // 5) logits = hs @ Wout + bout, remap to [B,T,V]
    gemm128k<<<dim3(79,25), 256>>>(hs, Hh, Hh,
        wb + OF_WOUT, Vv, bout, nullptr, out, Vv, Vv, MODE_REMAP,
        nullptr, nullptr);
}